// round 15
// baseline (speedup 1.0000x reference)
#include <cuda_runtime.h>
#include <cuda_fp16.h>
#include <math.h>
#include <stdint.h>

// Problem dims
#define BB   256
#define SS   16
#define HH   8
#define HSD  128
#define DD   1024
#define MM   1024
#define BSR  (BB*SS)
#define BSMN ((size_t)BSR*MM)

// Scratch (__device__ globals; no allocs allowed)
__device__ float  g_x[4 * BB * MM];        // [4][B][M] fp32 (z=1..3 used)
__device__ __half g_xh[BB * MM];           // fp16 x_emb (attn kv row 16)
__device__ __half g_acc[4][BSR * MM];      // raw GEMM results (fp16): g, f, i, o
__device__ __half g_mph[BSR * MM];         // fp16 memory proposal
__device__ __half g_hh[BSR * MM];          // fp16 h_state
__device__ __half g_msh[BSR * MM];         // fp16 m_state
__device__ __half g_inph[BB * DD];         // fp16 inputs
__device__ __half g_wh[8 * MM * MM];       // fp16 weights: Wg,Wuf,Wui,Wuo,Wemb,Wwf,Wwi,Wwo
__device__ int    g_cnt[256];              // per-tile arrival counters (zero-init)

__device__ __forceinline__ float sigf(float x) { return 1.0f / (1.0f + expf(-x)); }

__device__ __forceinline__ void cpa16(void* dst, const void* src) {
    unsigned s = (unsigned)__cvta_generic_to_shared(dst);
    asm volatile("cp.async.cg.shared.global [%0], [%1], 16;" :: "r"(s), "l"(src));
}
__device__ __forceinline__ void cpa_commit() { asm volatile("cp.async.commit_group;"); }
__device__ __forceinline__ void cpa_wait0()  { asm volatile("cp.async.wait_group 0;"); }
__device__ __forceinline__ void cpa_wait1()  { asm volatile("cp.async.wait_group 1;"); }

__device__ __forceinline__ void ldsm4(unsigned* r, unsigned addr) {
    asm volatile("ldmatrix.sync.aligned.m8n8.x4.shared.b16 {%0,%1,%2,%3}, [%4];"
                 : "=r"(r[0]), "=r"(r[1]), "=r"(r[2]), "=r"(r[3]) : "r"(addr));
}
__device__ __forceinline__ void ldsm4t(unsigned* r, unsigned addr) {
    asm volatile("ldmatrix.sync.aligned.m8n8.x4.trans.shared.b16 {%0,%1,%2,%3}, [%4];"
                 : "=r"(r[0]), "=r"(r[1]), "=r"(r[2]), "=r"(r[3]) : "r"(addr));
}
__device__ __forceinline__ void mma16(float* c, const unsigned* a, const unsigned* b) {
    asm volatile(
        "mma.sync.aligned.m16n8k16.row.col.f32.f16.f16.f32 "
        "{%0,%1,%2,%3}, {%4,%5,%6,%7}, {%8,%9}, {%0,%1,%2,%3};"
        : "+f"(c[0]), "+f"(c[1]), "+f"(c[2]), "+f"(c[3])
        : "r"(a[0]), "r"(a[1]), "r"(a[2]), "r"(a[3]), "r"(b[0]), "r"(b[1]));
}

// Swizzled smem byte offsets (conflict-free for ldmatrix + cp.async):
__device__ __forceinline__ int a_off(int m, int c) {
    return m * 64 + ((c ^ ((m >> 1) & 3)) << 4);
}
__device__ __forceinline__ int b_off(int k, int c) {
    return k * 256 + ((c ^ (k & 7)) << 4);
}

#define A_TILE 8192
#define B_TILE 8192

// ---------------------------------------------------------------------------
// fp16 GEMM body (R10-proven): 256 threads, 8 warps, warp tile 64x32,
// BK=32, 2-stage cp.async.
// ---------------------------------------------------------------------------
__device__ __forceinline__ void gemm_body_h(
    const __half* __restrict__ Ah, const __half* __restrict__ Wh,
    int row0, int col0, int kiters, char* smem, float acc[4][4][4])
{
    const int tid  = threadIdx.x;
    const int lane = tid & 31, wid = tid >> 5;
    const int wr = wid >> 2, wc = wid & 3;

    char* smA[2] = { smem,             smem + A_TILE };
    char* smB[2] = { smem + 2*A_TILE,  smem + 2*A_TILE + B_TILE };

    const int a_lr = ((lane >> 3) & 1) * 8 + (lane & 7);
    const int a_lc = (lane >> 4) & 1;
    const int b_lk = (lane >> 3) * 8 + (lane & 7);

    #pragma unroll
    for (int i = 0; i < 2; i++) {
        const int id = tid + i * 256;
        const int am_ = id >> 2, ac_ = id & 3;
        cpa16(smA[0] + a_off(am_, ac_), &Ah[(size_t)(row0 + am_) * MM + ac_ * 8]);
        const int bk_ = id >> 4, bc_ = id & 15;
        cpa16(smB[0] + b_off(bk_, bc_), &Wh[(size_t)bk_ * MM + col0 + bc_ * 8]);
    }
    cpa_commit();

    int buf = 0;
    for (int kt = 0; kt < kiters; kt++) {
        if (kt + 1 < kiters) {
            const int k0 = (kt + 1) * 32;
            #pragma unroll
            for (int i = 0; i < 2; i++) {
                const int id = tid + i * 256;
                const int am_ = id >> 2, ac_ = id & 3;
                cpa16(smA[buf ^ 1] + a_off(am_, ac_),
                      &Ah[(size_t)(row0 + am_) * MM + k0 + ac_ * 8]);
                const int bk_ = id >> 4, bc_ = id & 15;
                cpa16(smB[buf ^ 1] + b_off(bk_, bc_),
                      &Wh[(size_t)(k0 + bk_) * MM + col0 + bc_ * 8]);
            }
            cpa_commit();
            cpa_wait1();
        } else {
            cpa_wait0();
        }
        __syncthreads();

        const unsigned sa = (unsigned)__cvta_generic_to_shared(smA[buf]);
        const unsigned sb = (unsigned)__cvta_generic_to_shared(smB[buf]);

        unsigned bf[4][4];
        #pragma unroll
        for (int nt = 0; nt < 4; nt++) {
            const int cn = wc * 4 + nt;
            ldsm4t(bf[nt], sb + b_off(b_lk, cn));
        }

        #pragma unroll
        for (int ks = 0; ks < 2; ks++) {
            unsigned am[4][4];
            #pragma unroll
            for (int mt = 0; mt < 4; mt++) {
                const int m = wr * 64 + mt * 16 + a_lr;
                ldsm4(am[mt], sa + a_off(m, ks * 2 + a_lc));
            }
            #pragma unroll
            for (int nt = 0; nt < 4; nt++) {
                #pragma unroll
                for (int mt = 0; mt < 4; mt++)
                    mma16(acc[mt][nt], am[mt], &bf[nt][ks * 2]);
            }
        }
        __syncthreads();
        buf ^= 1;
    }
}

// ---------------------------------------------------------------------------
// Convert kernels: fp32 -> fp16
// ---------------------------------------------------------------------------
__global__ __launch_bounds__(256) void conv_w(
    const float* __restrict__ Wg,   const float* __restrict__ Wuf,
    const float* __restrict__ Wui,  const float* __restrict__ Wuo,
    const float* __restrict__ Wemb, const float* __restrict__ Wwf,
    const float* __restrict__ Wwi,  const float* __restrict__ Wwo)
{
    const float* srcs[8] = { Wg, Wuf, Wui, Wuo, Wemb, Wwf, Wwi, Wwo };
    const float* s = srcs[blockIdx.z];
    const size_t i = ((size_t)blockIdx.x * 256 + threadIdx.x) * 4;
    float4 v = *(const float4*)&s[i];
    __half2* d = (__half2*)&g_wh[(size_t)blockIdx.z * MM * MM + i];
    d[0] = __floats2half2_rn(v.x, v.y);
    d[1] = __floats2half2_rn(v.z, v.w);
}

__global__ __launch_bounds__(256) void conv_s(
    const float* __restrict__ hstate, const float* __restrict__ inp,
    const float* __restrict__ mstate)
{
    const size_t i = ((size_t)blockIdx.x * 256 + threadIdx.x) * 4;
    const size_t HSZ = (size_t)BSR * MM;
    const size_t ISZ = (size_t)BB * DD;
    const float* src; __half* dst; size_t j;
    if (i < HSZ)            { src = hstate; dst = g_hh;   j = i; }
    else if (i < HSZ + ISZ) { src = inp;    dst = g_inph; j = i - HSZ; }
    else                    { src = mstate; dst = g_msh;  j = i - HSZ - ISZ; }
    float4 v = *(const float4*)&src[j];
    __half2* d = (__half2*)&dst[j];
    d[0] = __floats2half2_rn(v.x, v.y);
    d[1] = __floats2half2_rn(v.z, v.w);
}

// ---------------------------------------------------------------------------
// Kernel A: input projections (fp16). z = blockIdx.z.
// z0 -> fp16 g_xh (+bias); z1-3 -> fp32 g_x.
// ---------------------------------------------------------------------------
__global__ __launch_bounds__(256, 2) void gemm_x_h(const float* __restrict__ bemb)
{
    __shared__ __align__(128) char smem[2 * (A_TILE + B_TILE)];
    const int z = blockIdx.z;
    const int row0 = blockIdx.y * 128, col0 = blockIdx.x * 128;

    float acc[4][4][4] = {};
    gemm_body_h(g_inph, g_wh + (size_t)(4 + z) * MM * MM, row0, col0, DD / 32,
                smem, acc);

    const int lane = threadIdx.x & 31, wid = threadIdx.x >> 5;
    const int wr = wid >> 2, wc = wid & 3;
    const int kq = lane & 3, gq = lane >> 2;

    #pragma unroll
    for (int nt = 0; nt < 4; nt++) {
        const int c = col0 + wc * 32 + nt * 8 + 2 * kq;
        float2 bv = make_float2(0.f, 0.f);
        if (z == 0) bv = *(const float2*)&bemb[c];
        #pragma unroll
        for (int mt = 0; mt < 4; mt++) {
            #pragma unroll
            for (int h = 0; h < 2; h++) {
                const int r = row0 + wr * 64 + mt * 16 + gq + h * 8;
                const float ox = acc[mt][nt][2 * h + 0] + bv.x;
                const float oy = acc[mt][nt][2 * h + 1] + bv.y;
                if (z == 0) {
                    *(__half2*)&g_xh[(size_t)r * MM + c] = __floats2half2_rn(ox, oy);
                } else {
                    float2 o; o.x = ox; o.y = oy;
                    *(float2*)&g_x[(size_t)z * BB * MM + (size_t)r * MM + c] = o;
                }
            }
        }
    }
}

// ---------------------------------------------------------------------------
// Kernel B: attention per (b, h) — fp16 kv in smem.
// ---------------------------------------------------------------------------
#define KVSTR 136

__global__ __launch_bounds__(256) void attn_kernel()
{
    __shared__ __align__(16) __half kvh[17 * KVSTR];
    __shared__ float sc[16][20];

    const int bh  = blockIdx.x;
    const int b   = bh >> 3;
    const int h   = bh & 7;
    const int tid = threadIdx.x;

    const __half* mb = g_msh + (size_t)b * SS * MM + h * HSD;

    for (int i = tid; i < 17 * 16; i += 256) {
        const int t = i >> 4, d8 = i & 15;
        const __half* src = (t < SS) ? &mb[(size_t)t * MM + d8 * 8]
                                     : &g_xh[(size_t)b * MM + h * HSD + d8 * 8];
        *(uint4*)&kvh[t * KVSTR + d8 * 8] = *(const uint4*)src;
    }
    __syncthreads();

    for (int p = tid; p < 16 * 17; p += 256) {
        const int s = p / 17, t = p % 17;
        const __half2* qr = (const __half2*)&kvh[s * KVSTR];
        const __half2* kr = (const __half2*)&kvh[t * KVSTR];
        float a0 = 0.f, a1 = 0.f;
        #pragma unroll
        for (int d2 = 0; d2 < 64; d2 += 2) {
            const float2 q0 = __half22float2(qr[d2]),     k0 = __half22float2(kr[d2]);
            const float2 q1 = __half22float2(qr[d2 + 1]), k1 = __half22float2(kr[d2 + 1]);
            a0 += q0.x * k0.x + q0.y * k0.y;
            a1 += q1.x * k1.x + q1.y * k1.y;
        }
        sc[s][t] = (a0 + a1) * 0.08838834764831845f;
    }
    __syncthreads();

    if (tid < 16) {
        float mx = sc[tid][0];
        #pragma unroll
        for (int t = 1; t < 17; t++) mx = fmaxf(mx, sc[tid][t]);
        float sum = 0.f;
        #pragma unroll
        for (int t = 0; t < 17; t++) { float e = expf(sc[tid][t] - mx); sc[tid][t] = e; sum += e; }
        const float inv = 1.0f / sum;
        #pragma unroll
        for (int t = 0; t < 17; t++) sc[tid][t] *= inv;
    }
    __syncthreads();

    {
        const int s = tid >> 4, d8 = tid & 15;
        float acc[8];
        {
            const __half2* r0 = (const __half2*)&kvh[s * KVSTR + d8 * 8];
            #pragma unroll
            for (int u = 0; u < 4; u++) {
                const float2 v = __half22float2(r0[u]);
                acc[2 * u] = v.x; acc[2 * u + 1] = v.y;
            }
        }
        #pragma unroll
        for (int t = 0; t < 17; t++) {
            const float p = sc[s][t];
            const __half2* rt = (const __half2*)&kvh[t * KVSTR + d8 * 8];
            #pragma unroll
            for (int u = 0; u < 4; u++) {
                const float2 v = __half22float2(rt[u]);
                acc[2 * u]     += p * v.x;
                acc[2 * u + 1] += p * v.y;
            }
        }
        const size_t idx = ((size_t)b * SS + s) * MM + h * HSD + d8 * 8;
        __half2 o[4];
        #pragma unroll
        for (int u = 0; u < 4; u++) o[u] = __floats2half2_rn(acc[2 * u], acc[2 * u + 1]);
        *(uint4*)&g_mph[idx] = *(uint4*)o;
    }
}

// ---------------------------------------------------------------------------
// fp16 -> 4 floats
// ---------------------------------------------------------------------------
__device__ __forceinline__ void ld4h(float* d, const __half* p) {
    const __half2* h2 = (const __half2*)p;
    const float2 lo = __half22float2(h2[0]), hi = __half22float2(h2[1]);
    d[0] = lo.x; d[1] = lo.y; d[2] = hi.x; d[3] = hi.y;
}

// ---------------------------------------------------------------------------
// Kernel C: big fp16 GEMM + LAST-ARRIVER fused gate epilogue.
// z = zbase + blockIdx.z. Tile (bx,by) gets 4 arrivals (one per z); the 4th
// CTA performs the gate math for the whole 128x128 tile.
// ---------------------------------------------------------------------------
__global__ __launch_bounds__(256, 2) void big_gemm_h(
    int zbase,
    const float* __restrict__ mstate,
    const float* __restrict__ bg,  const float* __restrict__ buf_,
    const float* __restrict__ bui, const float* __restrict__ buo,
    float* __restrict__ out)
{
    __shared__ __align__(128) char smem[2 * (A_TILE + B_TILE)];
    __shared__ int s_old;
    const int z = zbase + blockIdx.z;
    const int row0 = blockIdx.y * 128, col0 = blockIdx.x * 128;

    const __half* A = (z == 0) ? g_mph : g_hh;
    const __half* W = g_wh + (size_t)z * MM * MM;

    float acc[4][4][4] = {};
    gemm_body_h(A, W, row0, col0, MM / 32, smem, acc);

    const int lane = threadIdx.x & 31, wid = threadIdx.x >> 5;
    const int wr = wid >> 2, wc = wid & 3;
    const int kq = lane & 3, gq = lane >> 2;

    __half* outp = g_acc[z];
    #pragma unroll
    for (int nt = 0; nt < 4; nt++) {
        const int c = col0 + wc * 32 + nt * 8 + 2 * kq;
        #pragma unroll
        for (int mt = 0; mt < 4; mt++) {
            #pragma unroll
            for (int h = 0; h < 2; h++) {
                const int r = row0 + wr * 64 + mt * 16 + gq + h * 8;
                *(__half2*)&outp[(size_t)r * MM + c] =
                    __floats2half2_rn(acc[mt][nt][2 * h + 0], acc[mt][nt][2 * h + 1]);
            }
        }
    }

    // ---- arrival counting ----
    __threadfence();                     // make tile stores visible device-wide
    __syncthreads();
    const int tile_id = blockIdx.y * 8 + blockIdx.x;
    if (threadIdx.x == 0) s_old = atomicAdd(&g_cnt[tile_id], 1);
    __syncthreads();
    if (s_old != 3) return;

    // ---- last arriver: fused gate epilogue for this 128x128 tile ----
    __threadfence();                     // order subsequent reads after count
    for (int i = threadIdx.x; i < 128 * 32; i += 256) {
        const int rr = i >> 5;
        const int cc = (i & 31) * 4;
        const int r = row0 + rr;
        const int c = col0 + cc;
        const size_t e = (size_t)r * MM + c;
        const int bidx = r >> 4;

        float vg[4], vf[4], vi[4], vo[4], mp[4];
        ld4h(vg, &g_acc[0][e]);
        ld4h(vf, &g_acc[1][e]);
        ld4h(vi, &g_acc[2][e]);
        ld4h(vo, &g_acc[3][e]);
        ld4h(mp, &g_mph[e]);

        const float4 mv  = *(const float4*)&mstate[e];
        const float4 wfv = *(const float4*)&g_x[(size_t)1 * BB * MM + (size_t)bidx * MM + c];
        const float4 wiv = *(const float4*)&g_x[(size_t)2 * BB * MM + (size_t)bidx * MM + c];
        const float4 wov = *(const float4*)&g_x[(size_t)3 * BB * MM + (size_t)bidx * MM + c];
        const float4 bgv = *(const float4*)&bg[c];
        const float4 bfv = *(const float4*)&buf_[c];
        const float4 biv = *(const float4*)&bui[c];
        const float4 bov = *(const float4*)&buo[c];

        float nm[4], nh[4];
        const float* mvp = &mv.x;
        const float* wfp = &wfv.x; const float* wip = &wiv.x; const float* wop = &wov.x;
        const float* bgp = &bgv.x; const float* bfp = &bfv.x;
        const float* bip = &biv.x; const float* bop = &bov.x;
        #pragma unroll
        for (int u = 0; u < 4; u++) {
            const float mpf = vg[u] + bgp[u] + mp[u];
            const float fgt = sigf(vf[u] + bfp[u] + wfp[u]);
            const float igt = sigf(vi[u] + bip[u] + wip[u]);
            const float ogt = sigf(vo[u] + bop[u] + wop[u]);
            nm[u] = sigf(mvp[u] * fgt + 1.0f) + mpf * sigf(igt);
            nh[u] = tanhf(mvp[u]) * sigf(ogt);
        }
        *(float4*)&out[e]        = *(float4*)nm;
        *(float4*)&out[BSMN + e] = *(float4*)nh;
    }
    if (threadIdx.x == 0) atomicExch(&g_cnt[tile_id], 0);   // replay-safe reset
}

// ---------------------------------------------------------------------------
// Side stream + events (host objects at load time; serial fallback on failure)
// ---------------------------------------------------------------------------
static cudaStream_t g_s2 = 0;
static cudaEvent_t  g_evA = 0, g_evB = 0;
static bool g_use2 = false;
namespace {
struct StreamInit {
    StreamInit() {
        g_use2 =
            cudaStreamCreateWithFlags(&g_s2, cudaStreamNonBlocking) == cudaSuccess &&
            cudaEventCreateWithFlags(&g_evA, cudaEventDisableTiming) == cudaSuccess &&
            cudaEventCreateWithFlags(&g_evB, cudaEventDisableTiming) == cudaSuccess;
    }
};
static StreamInit g_stream_init;
}

// ---------------------------------------------------------------------------
extern "C" void kernel_launch(void* const* d_in, const int* in_sizes, int n_in,
                              void* d_out, int out_size)
{
    const float* inputs  = (const float*)d_in[0];
    const float* h_state = (const float*)d_in[1];
    const float* m_state = (const float*)d_in[2];
    const float* W_emb   = (const float*)d_in[3];
    const float* b_emb   = (const float*)d_in[4];
    const float* W_g     = (const float*)d_in[5];
    const float* b_g     = (const float*)d_in[6];
    const float* W_wf    = (const float*)d_in[7];
    const float* W_wi    = (const float*)d_in[8];
    const float* W_wo    = (const float*)d_in[9];
    const float* W_uf    = (const float*)d_in[10];
    const float* b_uf    = (const float*)d_in[11];
    const float* W_ui    = (const float*)d_in[12];
    const float* b_ui    = (const float*)d_in[13];
    const float* W_uo    = (const float*)d_in[14];
    const float* b_uo    = (const float*)d_in[15];
    float* out = (float*)d_out;

    // fp32 -> fp16 conversions (default stream)
    conv_w<<<dim3(MM * MM / 1024, 1, 8), 256>>>(W_g, W_uf, W_ui, W_uo,
                                                W_emb, W_wf, W_wi, W_wo);
    conv_s<<<(2 * BSR * MM + BB * DD) / 1024, 256>>>(h_state, inputs, m_state);

    if (g_use2) {
        cudaEventRecord(g_evA, 0);
        // s1 chain: gemm_x (all 4) -> attn -> big z0 (+fused epilogue)
        gemm_x_h<<<dim3(8, 2, 4), 256>>>(b_emb);
        // s2: big GEMMs z1-3 (depend only on conversions)
        cudaStreamWaitEvent(g_s2, g_evA, 0);
        big_gemm_h<<<dim3(8, 32, 3), 256, 0, g_s2>>>(1, m_state, b_g, b_uf, b_ui, b_uo, out);
        cudaEventRecord(g_evB, g_s2);
        attn_kernel<<<BB * HH, 256>>>();
        big_gemm_h<<<dim3(8, 32, 1), 256>>>(0, m_state, b_g, b_uf, b_ui, b_uo, out);
        // join side stream back into capture (no trailing kernel needed)
        cudaStreamWaitEvent(0, g_evB, 0);
    } else {
        gemm_x_h<<<dim3(8, 2, 4), 256>>>(b_emb);
        attn_kernel<<<BB * HH, 256>>>();
        big_gemm_h<<<dim3(8, 32, 3), 256>>>(1, m_state, b_g, b_uf, b_ui, b_uo, out);
        big_gemm_h<<<dim3(8, 32, 1), 256>>>(0, m_state, b_g, b_uf, b_ui, b_uo, out);
    }
}

// round 16
// speedup vs baseline: 1.1093x; 1.1093x over previous
#include <cuda_runtime.h>
#include <cuda_fp16.h>
#include <math.h>
#include <stdint.h>

// Problem dims
#define BB   256
#define SS   16
#define HH   8
#define HSD  128
#define DD   1024
#define MM   1024
#define BSR  (BB*SS)
#define BSMN ((size_t)BSR*MM)

// Scratch (__device__ globals; no allocs allowed)
__device__ float  g_x[4 * BB * MM];        // [4][B][M] fp32 (z=1..3 used)
__device__ __half g_xh[BB * MM];           // fp16 x_emb (attn kv row 16)
__device__ __half g_acc[4][BSR * MM];      // raw GEMM results (fp16): g, f, i, o
__device__ __half g_mph[BSR * MM];         // fp16 memory proposal
__device__ __half g_hh[BSR * MM];          // fp16 h_state
__device__ __half g_msh[BSR * MM];         // fp16 m_state
__device__ __half g_inph[BB * DD];         // fp16 inputs
__device__ __half g_wh[8 * MM * MM];       // fp16 weights: Wg,Wuf,Wui,Wuo,Wemb,Wwf,Wwi,Wwo

__device__ __forceinline__ float sigf(float x) { return 1.0f / (1.0f + expf(-x)); }
// Fast-math variants (epilogue only): __expf rel-err ~1e-6 << tolerance.
__device__ __forceinline__ float sigf_fast(float x) { return 1.0f / (1.0f + __expf(-x)); }
__device__ __forceinline__ float tanh_fast(float x) {
    return 2.0f / (1.0f + __expf(-2.0f * x)) - 1.0f;
}

__device__ __forceinline__ void cpa16(void* dst, const void* src) {
    unsigned s = (unsigned)__cvta_generic_to_shared(dst);
    asm volatile("cp.async.cg.shared.global [%0], [%1], 16;" :: "r"(s), "l"(src));
}
__device__ __forceinline__ void cpa_commit() { asm volatile("cp.async.commit_group;"); }
__device__ __forceinline__ void cpa_wait0()  { asm volatile("cp.async.wait_group 0;"); }
__device__ __forceinline__ void cpa_wait1()  { asm volatile("cp.async.wait_group 1;"); }

__device__ __forceinline__ void ldsm4(unsigned* r, unsigned addr) {
    asm volatile("ldmatrix.sync.aligned.m8n8.x4.shared.b16 {%0,%1,%2,%3}, [%4];"
                 : "=r"(r[0]), "=r"(r[1]), "=r"(r[2]), "=r"(r[3]) : "r"(addr));
}
__device__ __forceinline__ void ldsm4t(unsigned* r, unsigned addr) {
    asm volatile("ldmatrix.sync.aligned.m8n8.x4.trans.shared.b16 {%0,%1,%2,%3}, [%4];"
                 : "=r"(r[0]), "=r"(r[1]), "=r"(r[2]), "=r"(r[3]) : "r"(addr));
}
__device__ __forceinline__ void mma16(float* c, const unsigned* a, const unsigned* b) {
    asm volatile(
        "mma.sync.aligned.m16n8k16.row.col.f32.f16.f16.f32 "
        "{%0,%1,%2,%3}, {%4,%5,%6,%7}, {%8,%9}, {%0,%1,%2,%3};"
        : "+f"(c[0]), "+f"(c[1]), "+f"(c[2]), "+f"(c[3])
        : "r"(a[0]), "r"(a[1]), "r"(a[2]), "r"(a[3]), "r"(b[0]), "r"(b[1]));
}

// Swizzled smem byte offsets (conflict-free for ldmatrix + cp.async):
__device__ __forceinline__ int a_off(int m, int c) {
    return m * 64 + ((c ^ ((m >> 1) & 3)) << 4);
}
__device__ __forceinline__ int b_off(int k, int c) {
    return k * 256 + ((c ^ (k & 7)) << 4);
}

#define A_TILE 8192
#define B_TILE 8192

// ---------------------------------------------------------------------------
// fp16 GEMM body (R10-proven): 256 threads, 8 warps, warp tile 64x32,
// BK=32, 2-stage cp.async.
// ---------------------------------------------------------------------------
__device__ __forceinline__ void gemm_body_h(
    const __half* __restrict__ Ah, const __half* __restrict__ Wh,
    int row0, int col0, int kiters, char* smem, float acc[4][4][4])
{
    const int tid  = threadIdx.x;
    const int lane = tid & 31, wid = tid >> 5;
    const int wr = wid >> 2, wc = wid & 3;

    char* smA[2] = { smem,             smem + A_TILE };
    char* smB[2] = { smem + 2*A_TILE,  smem + 2*A_TILE + B_TILE };

    const int a_lr = ((lane >> 3) & 1) * 8 + (lane & 7);
    const int a_lc = (lane >> 4) & 1;
    const int b_lk = (lane >> 3) * 8 + (lane & 7);

    #pragma unroll
    for (int i = 0; i < 2; i++) {
        const int id = tid + i * 256;
        const int am_ = id >> 2, ac_ = id & 3;
        cpa16(smA[0] + a_off(am_, ac_), &Ah[(size_t)(row0 + am_) * MM + ac_ * 8]);
        const int bk_ = id >> 4, bc_ = id & 15;
        cpa16(smB[0] + b_off(bk_, bc_), &Wh[(size_t)bk_ * MM + col0 + bc_ * 8]);
    }
    cpa_commit();

    int buf = 0;
    for (int kt = 0; kt < kiters; kt++) {
        if (kt + 1 < kiters) {
            const int k0 = (kt + 1) * 32;
            #pragma unroll
            for (int i = 0; i < 2; i++) {
                const int id = tid + i * 256;
                const int am_ = id >> 2, ac_ = id & 3;
                cpa16(smA[buf ^ 1] + a_off(am_, ac_),
                      &Ah[(size_t)(row0 + am_) * MM + k0 + ac_ * 8]);
                const int bk_ = id >> 4, bc_ = id & 15;
                cpa16(smB[buf ^ 1] + b_off(bk_, bc_),
                      &Wh[(size_t)(k0 + bk_) * MM + col0 + bc_ * 8]);
            }
            cpa_commit();
            cpa_wait1();
        } else {
            cpa_wait0();
        }
        __syncthreads();

        const unsigned sa = (unsigned)__cvta_generic_to_shared(smA[buf]);
        const unsigned sb = (unsigned)__cvta_generic_to_shared(smB[buf]);

        unsigned bf[4][4];
        #pragma unroll
        for (int nt = 0; nt < 4; nt++) {
            const int cn = wc * 4 + nt;
            ldsm4t(bf[nt], sb + b_off(b_lk, cn));
        }

        #pragma unroll
        for (int ks = 0; ks < 2; ks++) {
            unsigned am[4][4];
            #pragma unroll
            for (int mt = 0; mt < 4; mt++) {
                const int m = wr * 64 + mt * 16 + a_lr;
                ldsm4(am[mt], sa + a_off(m, ks * 2 + a_lc));
            }
            #pragma unroll
            for (int nt = 0; nt < 4; nt++) {
                #pragma unroll
                for (int mt = 0; mt < 4; mt++)
                    mma16(acc[mt][nt], am[mt], &bf[nt][ks * 2]);
            }
        }
        __syncthreads();
        buf ^= 1;
    }
}

// ---------------------------------------------------------------------------
// Convert kernels: fp32 -> fp16
// ---------------------------------------------------------------------------
__global__ __launch_bounds__(256) void conv_w(
    const float* __restrict__ Wg,   const float* __restrict__ Wuf,
    const float* __restrict__ Wui,  const float* __restrict__ Wuo,
    const float* __restrict__ Wemb, const float* __restrict__ Wwf,
    const float* __restrict__ Wwi,  const float* __restrict__ Wwo)
{
    const float* srcs[8] = { Wg, Wuf, Wui, Wuo, Wemb, Wwf, Wwi, Wwo };
    const float* s = srcs[blockIdx.z];
    const size_t i = ((size_t)blockIdx.x * 256 + threadIdx.x) * 4;
    float4 v = *(const float4*)&s[i];
    __half2* d = (__half2*)&g_wh[(size_t)blockIdx.z * MM * MM + i];
    d[0] = __floats2half2_rn(v.x, v.y);
    d[1] = __floats2half2_rn(v.z, v.w);
}

// h_state -> g_hh, inputs -> g_inph, m_state -> g_msh
__global__ __launch_bounds__(256) void conv_s(
    const float* __restrict__ hstate, const float* __restrict__ inp,
    const float* __restrict__ mstate)
{
    const size_t i = ((size_t)blockIdx.x * 256 + threadIdx.x) * 4;
    const size_t HSZ = (size_t)BSR * MM;
    const size_t ISZ = (size_t)BB * DD;
    const float* src; __half* dst; size_t j;
    if (i < HSZ)            { src = hstate; dst = g_hh;   j = i; }
    else if (i < HSZ + ISZ) { src = inp;    dst = g_inph; j = i - HSZ; }
    else                    { src = mstate; dst = g_msh;  j = i - HSZ - ISZ; }
    float4 v = *(const float4*)&src[j];
    __half2* d = (__half2*)&dst[j];
    d[0] = __floats2half2_rn(v.x, v.y);
    d[1] = __floats2half2_rn(v.z, v.w);
}

// ---------------------------------------------------------------------------
// Kernel A: input projections (fp16). z = blockIdx.z.
// z0 -> fp16 g_xh (+bias); z1-3 -> fp32 g_x.
// ---------------------------------------------------------------------------
__global__ __launch_bounds__(256, 2) void gemm_x_h(const float* __restrict__ bemb)
{
    __shared__ __align__(128) char smem[2 * (A_TILE + B_TILE)];
    const int z = blockIdx.z;
    const int row0 = blockIdx.y * 128, col0 = blockIdx.x * 128;

    float acc[4][4][4] = {};
    gemm_body_h(g_inph, g_wh + (size_t)(4 + z) * MM * MM, row0, col0, DD / 32,
                smem, acc);

    const int lane = threadIdx.x & 31, wid = threadIdx.x >> 5;
    const int wr = wid >> 2, wc = wid & 3;
    const int kq = lane & 3, gq = lane >> 2;

    #pragma unroll
    for (int nt = 0; nt < 4; nt++) {
        const int c = col0 + wc * 32 + nt * 8 + 2 * kq;
        float2 bv = make_float2(0.f, 0.f);
        if (z == 0) bv = *(const float2*)&bemb[c];
        #pragma unroll
        for (int mt = 0; mt < 4; mt++) {
            #pragma unroll
            for (int h = 0; h < 2; h++) {
                const int r = row0 + wr * 64 + mt * 16 + gq + h * 8;
                const float ox = acc[mt][nt][2 * h + 0] + bv.x;
                const float oy = acc[mt][nt][2 * h + 1] + bv.y;
                if (z == 0) {
                    *(__half2*)&g_xh[(size_t)r * MM + c] = __floats2half2_rn(ox, oy);
                } else {
                    float2 o; o.x = ox; o.y = oy;
                    *(float2*)&g_x[(size_t)z * BB * MM + (size_t)r * MM + c] = o;
                }
            }
        }
    }
}

// ---------------------------------------------------------------------------
// Kernel B: attention per (b, h) — fp16 kv in smem.
// ---------------------------------------------------------------------------
#define KVSTR 136

__global__ __launch_bounds__(256) void attn_kernel()
{
    __shared__ __align__(16) __half kvh[17 * KVSTR];
    __shared__ float sc[16][20];

    const int bh  = blockIdx.x;
    const int b   = bh >> 3;
    const int h   = bh & 7;
    const int tid = threadIdx.x;

    const __half* mb = g_msh + (size_t)b * SS * MM + h * HSD;

    for (int i = tid; i < 17 * 16; i += 256) {
        const int t = i >> 4, d8 = i & 15;
        const __half* src = (t < SS) ? &mb[(size_t)t * MM + d8 * 8]
                                     : &g_xh[(size_t)b * MM + h * HSD + d8 * 8];
        *(uint4*)&kvh[t * KVSTR + d8 * 8] = *(const uint4*)src;
    }
    __syncthreads();

    for (int p = tid; p < 16 * 17; p += 256) {
        const int s = p / 17, t = p % 17;
        const __half2* qr = (const __half2*)&kvh[s * KVSTR];
        const __half2* kr = (const __half2*)&kvh[t * KVSTR];
        float a0 = 0.f, a1 = 0.f;
        #pragma unroll
        for (int d2 = 0; d2 < 64; d2 += 2) {
            const float2 q0 = __half22float2(qr[d2]),     k0 = __half22float2(kr[d2]);
            const float2 q1 = __half22float2(qr[d2 + 1]), k1 = __half22float2(kr[d2 + 1]);
            a0 += q0.x * k0.x + q0.y * k0.y;
            a1 += q1.x * k1.x + q1.y * k1.y;
        }
        sc[s][t] = (a0 + a1) * 0.08838834764831845f;
    }
    __syncthreads();

    if (tid < 16) {
        float mx = sc[tid][0];
        #pragma unroll
        for (int t = 1; t < 17; t++) mx = fmaxf(mx, sc[tid][t]);
        float sum = 0.f;
        #pragma unroll
        for (int t = 0; t < 17; t++) { float e = expf(sc[tid][t] - mx); sc[tid][t] = e; sum += e; }
        const float inv = 1.0f / sum;
        #pragma unroll
        for (int t = 0; t < 17; t++) sc[tid][t] *= inv;
    }
    __syncthreads();

    {
        const int s = tid >> 4, d8 = tid & 15;
        float acc[8];
        {
            const __half2* r0 = (const __half2*)&kvh[s * KVSTR + d8 * 8];
            #pragma unroll
            for (int u = 0; u < 4; u++) {
                const float2 v = __half22float2(r0[u]);
                acc[2 * u] = v.x; acc[2 * u + 1] = v.y;
            }
        }
        #pragma unroll
        for (int t = 0; t < 17; t++) {
            const float p = sc[s][t];
            const __half2* rt = (const __half2*)&kvh[t * KVSTR + d8 * 8];
            #pragma unroll
            for (int u = 0; u < 4; u++) {
                const float2 v = __half22float2(rt[u]);
                acc[2 * u]     += p * v.x;
                acc[2 * u + 1] += p * v.y;
            }
        }
        const size_t idx = ((size_t)b * SS + s) * MM + h * HSD + d8 * 8;
        __half2 o[4];
        #pragma unroll
        for (int u = 0; u < 4; u++) o[u] = __floats2half2_rn(acc[2 * u], acc[2 * u + 1]);
        *(uint4*)&g_mph[idx] = *(uint4*)o;
    }
}

// ---------------------------------------------------------------------------
// Kernel C: big fp16 GEMM. z = zbase + blockIdx.z.
// ---------------------------------------------------------------------------
__global__ __launch_bounds__(256, 2) void big_gemm_h(int zbase)
{
    __shared__ __align__(128) char smem[2 * (A_TILE + B_TILE)];
    const int z = zbase + blockIdx.z;
    const int row0 = blockIdx.y * 128, col0 = blockIdx.x * 128;

    const __half* A = (z == 0) ? g_mph : g_hh;
    const __half* W = g_wh + (size_t)z * MM * MM;

    float acc[4][4][4] = {};
    gemm_body_h(A, W, row0, col0, MM / 32, smem, acc);

    const int lane = threadIdx.x & 31, wid = threadIdx.x >> 5;
    const int wr = wid >> 2, wc = wid & 3;
    const int kq = lane & 3, gq = lane >> 2;

    __half* outp = g_acc[z];
    #pragma unroll
    for (int nt = 0; nt < 4; nt++) {
        const int c = col0 + wc * 32 + nt * 8 + 2 * kq;
        #pragma unroll
        for (int mt = 0; mt < 4; mt++) {
            #pragma unroll
            for (int h = 0; h < 2; h++) {
                const int r = row0 + wr * 64 + mt * 16 + gq + h * 8;
                *(__half2*)&outp[(size_t)r * MM + c] =
                    __floats2half2_rn(acc[mt][nt][2 * h + 0], acc[mt][nt][2 * h + 1]);
            }
        }
    }
}

// ---------------------------------------------------------------------------
// Kernel D: streaming gate epilogue (fast-math transcendentals).
// ---------------------------------------------------------------------------
__device__ __forceinline__ void ld4h(float* d, const __half* p) {
    const __half2* h2 = (const __half2*)p;
    const float2 lo = __half22float2(h2[0]), hi = __half22float2(h2[1]);
    d[0] = lo.x; d[1] = lo.y; d[2] = hi.x; d[3] = hi.y;
}

__global__ __launch_bounds__(256) void gate_epilogue(
    const float* __restrict__ mstate,
    const float* __restrict__ bg,  const float* __restrict__ buf_,
    const float* __restrict__ bui, const float* __restrict__ buo,
    float* __restrict__ out)
{
    const size_t e = ((size_t)blockIdx.x * 256 + threadIdx.x) * 4;
    const int r = (int)(e >> 10);
    const int c = (int)(e & 1023);
    const int bidx = r >> 4;

    float vg[4], vf[4], vi[4], vo[4], mp[4];
    ld4h(vg, &g_acc[0][e]);
    ld4h(vf, &g_acc[1][e]);
    ld4h(vi, &g_acc[2][e]);
    ld4h(vo, &g_acc[3][e]);
    ld4h(mp, &g_mph[e]);

    const float4 mv  = *(const float4*)&mstate[e];
    const float4 wfv = *(const float4*)&g_x[(size_t)1 * BB * MM + (size_t)bidx * MM + c];
    const float4 wiv = *(const float4*)&g_x[(size_t)2 * BB * MM + (size_t)bidx * MM + c];
    const float4 wov = *(const float4*)&g_x[(size_t)3 * BB * MM + (size_t)bidx * MM + c];
    const float4 bgv = *(const float4*)&bg[c];
    const float4 bfv = *(const float4*)&buf_[c];
    const float4 biv = *(const float4*)&bui[c];
    const float4 bov = *(const float4*)&buo[c];

    float nm[4], nh[4];
    const float* mvp = &mv.x;
    const float* wfp = &wfv.x; const float* wip = &wiv.x; const float* wop = &wov.x;
    const float* bgp = &bgv.x; const float* bfp = &bfv.x;
    const float* bip = &biv.x; const float* bop = &bov.x;
    #pragma unroll
    for (int u = 0; u < 4; u++) {
        const float mpf = vg[u] + bgp[u] + mp[u];
        const float fgt = sigf_fast(vf[u] + bfp[u] + wfp[u]);
        const float igt = sigf_fast(vi[u] + bip[u] + wip[u]);
        const float ogt = sigf_fast(vo[u] + bop[u] + wop[u]);
        nm[u] = sigf_fast(mvp[u] * fgt + 1.0f) + mpf * sigf_fast(igt);
        nh[u] = tanh_fast(mvp[u]) * sigf_fast(ogt);
    }
    *(float4*)&out[e]        = *(float4*)nm;
    *(float4*)&out[BSMN + e] = *(float4*)nh;
}

// ---------------------------------------------------------------------------
// Side stream + events (host objects at load time; serial fallback on failure)
// ---------------------------------------------------------------------------
static cudaStream_t g_s2 = 0;
static cudaEvent_t  g_evA = 0, g_evB = 0;
static bool g_use2 = false;
namespace {
struct StreamInit {
    StreamInit() {
        g_use2 =
            cudaStreamCreateWithFlags(&g_s2, cudaStreamNonBlocking) == cudaSuccess &&
            cudaEventCreateWithFlags(&g_evA, cudaEventDisableTiming) == cudaSuccess &&
            cudaEventCreateWithFlags(&g_evB, cudaEventDisableTiming) == cudaSuccess;
    }
};
static StreamInit g_stream_init;
}

// ---------------------------------------------------------------------------
extern "C" void kernel_launch(void* const* d_in, const int* in_sizes, int n_in,
                              void* d_out, int out_size)
{
    const float* inputs  = (const float*)d_in[0];
    const float* h_state = (const float*)d_in[1];
    const float* m_state = (const float*)d_in[2];
    const float* W_emb   = (const float*)d_in[3];
    const float* b_emb   = (const float*)d_in[4];
    const float* W_g     = (const float*)d_in[5];
    const float* b_g     = (const float*)d_in[6];
    const float* W_wf    = (const float*)d_in[7];
    const float* W_wi    = (const float*)d_in[8];
    const float* W_wo    = (const float*)d_in[9];
    const float* W_uf    = (const float*)d_in[10];
    const float* b_uf    = (const float*)d_in[11];
    const float* W_ui    = (const float*)d_in[12];
    const float* b_ui    = (const float*)d_in[13];
    const float* W_uo    = (const float*)d_in[14];
    const float* b_uo    = (const float*)d_in[15];
    float* out = (float*)d_out;

    // fp32 -> fp16 conversions (default stream; R10-proven schedule)
    conv_w<<<dim3(MM * MM / 1024, 1, 8), 256>>>(W_g, W_uf, W_ui, W_uo,
                                                W_emb, W_wf, W_wi, W_wo);
    conv_s<<<(2 * BSR * MM + BB * DD) / 1024, 256>>>(h_state, inputs, m_state);

    if (g_use2) {
        cudaEventRecord(g_evA, 0);
        // s1 chain: gemm_x (all 4) -> attn -> big z0
        gemm_x_h<<<dim3(8, 2, 4), 256>>>(b_emb);
        // s2: big GEMMs z1-3 (depend only on conversions)
        cudaStreamWaitEvent(g_s2, g_evA, 0);
        big_gemm_h<<<dim3(8, 32, 3), 256, 0, g_s2>>>(1);
        cudaEventRecord(g_evB, g_s2);
        attn_kernel<<<BB * HH, 256>>>();
        big_gemm_h<<<dim3(8, 32, 1), 256>>>(0);
        // join before epilogue
        cudaStreamWaitEvent(0, g_evB, 0);
        gate_epilogue<<<(BSR * MM) / (256 * 4), 256>>>(m_state, b_g, b_uf, b_ui, b_uo, out);
    } else {
        gemm_x_h<<<dim3(8, 2, 4), 256>>>(b_emb);
        attn_kernel<<<BB * HH, 256>>>();
        big_gemm_h<<<dim3(8, 32, 3), 256>>>(1);
        big_gemm_h<<<dim3(8, 32, 1), 256>>>(0);
        gate_epilogue<<<(BSR * MM) / (256 * 4), 256>>>(m_state, b_g, b_uf, b_ui, b_uo, out);
    }
}

// round 17
// speedup vs baseline: 1.1237x; 1.0130x over previous
#include <cuda_runtime.h>
#include <cuda_fp16.h>
#include <math.h>
#include <stdint.h>

// Problem dims
#define BB   256
#define SS   16
#define HH   8
#define HSD  128
#define DD   1024
#define MM   1024
#define BSR  (BB*SS)
#define BSMN ((size_t)BSR*MM)

// Scratch (__device__ globals; no allocs allowed)
__device__ __half g_xh[BB * MM];           // fp16 x_emb (attn kv row 16)
__device__ __half g_xwh[3 * BB * MM];      // fp16 wx_f, wx_i, wx_o
__device__ __half g_acc[4][BSR * MM];      // raw GEMM results (fp16): g, f, i, o
__device__ __half g_mph[BSR * MM];         // fp16 memory proposal
__device__ __half g_hh[BSR * MM];          // fp16 h_state
__device__ __half g_inph[BB * DD];         // fp16 inputs
__device__ __half g_wh[8 * MM * MM];       // fp16 weights: Wg,Wuf,Wui,Wuo,Wemb,Wwf,Wwi,Wwo

__device__ __forceinline__ float sigf_fast(float x) { return 1.0f / (1.0f + __expf(-x)); }
__device__ __forceinline__ float tanh_fast(float x) {
    return 2.0f / (1.0f + __expf(-2.0f * x)) - 1.0f;
}

__device__ __forceinline__ void cpa16(void* dst, const void* src) {
    unsigned s = (unsigned)__cvta_generic_to_shared(dst);
    asm volatile("cp.async.cg.shared.global [%0], [%1], 16;" :: "r"(s), "l"(src));
}
__device__ __forceinline__ void cpa_commit() { asm volatile("cp.async.commit_group;"); }
__device__ __forceinline__ void cpa_wait0()  { asm volatile("cp.async.wait_group 0;"); }
__device__ __forceinline__ void cpa_wait1()  { asm volatile("cp.async.wait_group 1;"); }

__device__ __forceinline__ void ldsm4(unsigned* r, unsigned addr) {
    asm volatile("ldmatrix.sync.aligned.m8n8.x4.shared.b16 {%0,%1,%2,%3}, [%4];"
                 : "=r"(r[0]), "=r"(r[1]), "=r"(r[2]), "=r"(r[3]) : "r"(addr));
}
__device__ __forceinline__ void ldsm4t(unsigned* r, unsigned addr) {
    asm volatile("ldmatrix.sync.aligned.m8n8.x4.trans.shared.b16 {%0,%1,%2,%3}, [%4];"
                 : "=r"(r[0]), "=r"(r[1]), "=r"(r[2]), "=r"(r[3]) : "r"(addr));
}
__device__ __forceinline__ void mma16(float* c, const unsigned* a, const unsigned* b) {
    asm volatile(
        "mma.sync.aligned.m16n8k16.row.col.f32.f16.f16.f32 "
        "{%0,%1,%2,%3}, {%4,%5,%6,%7}, {%8,%9}, {%0,%1,%2,%3};"
        : "+f"(c[0]), "+f"(c[1]), "+f"(c[2]), "+f"(c[3])
        : "r"(a[0]), "r"(a[1]), "r"(a[2]), "r"(a[3]), "r"(b[0]), "r"(b[1]));
}

// Swizzled smem byte offsets (conflict-free for ldmatrix + cp.async):
__device__ __forceinline__ int a_off(int m, int c) {
    return m * 64 + ((c ^ ((m >> 1) & 3)) << 4);
}
__device__ __forceinline__ int b_off(int k, int c) {
    return k * 256 + ((c ^ (k & 7)) << 4);
}

#define A_TILE 8192
#define B_TILE 8192

// ---------------------------------------------------------------------------
// fp16 GEMM body (R10-proven): 256 threads, 8 warps, warp tile 64x32,
// BK=32, 2-stage cp.async.
// ---------------------------------------------------------------------------
__device__ __forceinline__ void gemm_body_h(
    const __half* __restrict__ Ah, const __half* __restrict__ Wh,
    int row0, int col0, int kiters, char* smem, float acc[4][4][4])
{
    const int tid  = threadIdx.x;
    const int lane = tid & 31, wid = tid >> 5;
    const int wr = wid >> 2, wc = wid & 3;

    char* smA[2] = { smem,             smem + A_TILE };
    char* smB[2] = { smem + 2*A_TILE,  smem + 2*A_TILE + B_TILE };

    const int a_lr = ((lane >> 3) & 1) * 8 + (lane & 7);
    const int a_lc = (lane >> 4) & 1;
    const int b_lk = (lane >> 3) * 8 + (lane & 7);

    #pragma unroll
    for (int i = 0; i < 2; i++) {
        const int id = tid + i * 256;
        const int am_ = id >> 2, ac_ = id & 3;
        cpa16(smA[0] + a_off(am_, ac_), &Ah[(size_t)(row0 + am_) * MM + ac_ * 8]);
        const int bk_ = id >> 4, bc_ = id & 15;
        cpa16(smB[0] + b_off(bk_, bc_), &Wh[(size_t)bk_ * MM + col0 + bc_ * 8]);
    }
    cpa_commit();

    int buf = 0;
    for (int kt = 0; kt < kiters; kt++) {
        if (kt + 1 < kiters) {
            const int k0 = (kt + 1) * 32;
            #pragma unroll
            for (int i = 0; i < 2; i++) {
                const int id = tid + i * 256;
                const int am_ = id >> 2, ac_ = id & 3;
                cpa16(smA[buf ^ 1] + a_off(am_, ac_),
                      &Ah[(size_t)(row0 + am_) * MM + k0 + ac_ * 8]);
                const int bk_ = id >> 4, bc_ = id & 15;
                cpa16(smB[buf ^ 1] + b_off(bk_, bc_),
                      &Wh[(size_t)(k0 + bk_) * MM + col0 + bc_ * 8]);
            }
            cpa_commit();
            cpa_wait1();
        } else {
            cpa_wait0();
        }
        __syncthreads();

        const unsigned sa = (unsigned)__cvta_generic_to_shared(smA[buf]);
        const unsigned sb = (unsigned)__cvta_generic_to_shared(smB[buf]);

        unsigned bf[4][4];
        #pragma unroll
        for (int nt = 0; nt < 4; nt++) {
            const int cn = wc * 4 + nt;
            ldsm4t(bf[nt], sb + b_off(b_lk, cn));
        }

        #pragma unroll
        for (int ks = 0; ks < 2; ks++) {
            unsigned am[4][4];
            #pragma unroll
            for (int mt = 0; mt < 4; mt++) {
                const int m = wr * 64 + mt * 16 + a_lr;
                ldsm4(am[mt], sa + a_off(m, ks * 2 + a_lc));
            }
            #pragma unroll
            for (int nt = 0; nt < 4; nt++) {
                #pragma unroll
                for (int mt = 0; mt < 4; mt++)
                    mma16(acc[mt][nt], am[mt], &bf[nt][ks * 2]);
            }
        }
        __syncthreads();
        buf ^= 1;
    }
}

// ---------------------------------------------------------------------------
// Convert kernels: fp32 -> fp16
// ---------------------------------------------------------------------------
__global__ __launch_bounds__(256) void conv_w(
    const float* __restrict__ Wg,   const float* __restrict__ Wuf,
    const float* __restrict__ Wui,  const float* __restrict__ Wuo,
    const float* __restrict__ Wemb, const float* __restrict__ Wwf,
    const float* __restrict__ Wwi,  const float* __restrict__ Wwo)
{
    const float* srcs[8] = { Wg, Wuf, Wui, Wuo, Wemb, Wwf, Wwi, Wwo };
    const float* s = srcs[blockIdx.z];
    const size_t i = ((size_t)blockIdx.x * 256 + threadIdx.x) * 4;
    float4 v = *(const float4*)&s[i];
    __half2* d = (__half2*)&g_wh[(size_t)blockIdx.z * MM * MM + i];
    d[0] = __floats2half2_rn(v.x, v.y);
    d[1] = __floats2half2_rn(v.z, v.w);
}

// h_state -> g_hh, inputs -> g_inph (m_state no longer converted)
__global__ __launch_bounds__(256) void conv_s(
    const float* __restrict__ hstate, const float* __restrict__ inp)
{
    const size_t i = ((size_t)blockIdx.x * 256 + threadIdx.x) * 4;
    const size_t HSZ = (size_t)BSR * MM;
    const float* src; __half* dst; size_t j;
    if (i < HSZ) { src = hstate; dst = g_hh;   j = i; }
    else         { src = inp;    dst = g_inph; j = i - HSZ; }
    float4 v = *(const float4*)&src[j];
    __half2* d = (__half2*)&dst[j];
    d[0] = __floats2half2_rn(v.x, v.y);
    d[1] = __floats2half2_rn(v.z, v.w);
}

// ---------------------------------------------------------------------------
// Kernel A: input projections (fp16). z = blockIdx.z.
// z0 -> g_xh (+bias); z1-3 -> g_xwh (all fp16 now).
// ---------------------------------------------------------------------------
__global__ __launch_bounds__(256, 2) void gemm_x_h(const float* __restrict__ bemb)
{
    __shared__ __align__(128) char smem[2 * (A_TILE + B_TILE)];
    const int z = blockIdx.z;
    const int row0 = blockIdx.y * 128, col0 = blockIdx.x * 128;

    float acc[4][4][4] = {};
    gemm_body_h(g_inph, g_wh + (size_t)(4 + z) * MM * MM, row0, col0, DD / 32,
                smem, acc);

    const int lane = threadIdx.x & 31, wid = threadIdx.x >> 5;
    const int wr = wid >> 2, wc = wid & 3;
    const int kq = lane & 3, gq = lane >> 2;

    __half* outp = (z == 0) ? g_xh : (g_xwh + (size_t)(z - 1) * BB * MM);
    #pragma unroll
    for (int nt = 0; nt < 4; nt++) {
        const int c = col0 + wc * 32 + nt * 8 + 2 * kq;
        float2 bv = make_float2(0.f, 0.f);
        if (z == 0) bv = *(const float2*)&bemb[c];
        #pragma unroll
        for (int mt = 0; mt < 4; mt++) {
            #pragma unroll
            for (int h = 0; h < 2; h++) {
                const int r = row0 + wr * 64 + mt * 16 + gq + h * 8;
                *(__half2*)&outp[(size_t)r * MM + c] =
                    __floats2half2_rn(acc[mt][nt][2 * h + 0] + bv.x,
                                      acc[mt][nt][2 * h + 1] + bv.y);
            }
        }
    }
}

// ---------------------------------------------------------------------------
// Kernel B: attention per (b, h) — reads fp32 m_state directly, fp16 kv smem.
// ---------------------------------------------------------------------------
#define KVSTR 136

__global__ __launch_bounds__(256) void attn_kernel(const float* __restrict__ mstate)
{
    __shared__ __align__(16) __half kvh[17 * KVSTR];
    __shared__ float sc[16][20];

    const int bh  = blockIdx.x;
    const int b   = bh >> 3;
    const int h   = bh & 7;
    const int tid = threadIdx.x;

    const float* mb = mstate + (size_t)b * SS * MM + h * HSD;

    // load kv tile: rows 0-15 from fp32 m_state (convert), row 16 from fp16 g_xh.
    // 17 rows x 32 chunks of 4 elements = 544 items
    for (int i = tid; i < 17 * 32; i += 256) {
        const int t = i >> 5, d4 = i & 31;
        __half2 o[2];
        if (t < SS) {
            const float4 v = *(const float4*)&mb[(size_t)t * MM + d4 * 4];
            o[0] = __floats2half2_rn(v.x, v.y);
            o[1] = __floats2half2_rn(v.z, v.w);
            *(uint2*)&kvh[t * KVSTR + d4 * 4] = *(uint2*)o;
        } else {
            *(uint2*)&kvh[t * KVSTR + d4 * 4] =
                *(const uint2*)&g_xh[(size_t)b * MM + h * HSD + d4 * 4];
        }
    }
    __syncthreads();

    for (int p = tid; p < 16 * 17; p += 256) {
        const int s = p / 17, t = p % 17;
        const __half2* qr = (const __half2*)&kvh[s * KVSTR];
        const __half2* kr = (const __half2*)&kvh[t * KVSTR];
        float a0 = 0.f, a1 = 0.f;
        #pragma unroll
        for (int d2 = 0; d2 < 64; d2 += 2) {
            const float2 q0 = __half22float2(qr[d2]),     k0 = __half22float2(kr[d2]);
            const float2 q1 = __half22float2(qr[d2 + 1]), k1 = __half22float2(kr[d2 + 1]);
            a0 += q0.x * k0.x + q0.y * k0.y;
            a1 += q1.x * k1.x + q1.y * k1.y;
        }
        sc[s][t] = (a0 + a1) * 0.08838834764831845f;
    }
    __syncthreads();

    if (tid < 16) {
        float mx = sc[tid][0];
        #pragma unroll
        for (int t = 1; t < 17; t++) mx = fmaxf(mx, sc[tid][t]);
        float sum = 0.f;
        #pragma unroll
        for (int t = 0; t < 17; t++) { float e = expf(sc[tid][t] - mx); sc[tid][t] = e; sum += e; }
        const float inv = 1.0f / sum;
        #pragma unroll
        for (int t = 0; t < 17; t++) sc[tid][t] *= inv;
    }
    __syncthreads();

    {
        const int s = tid >> 4, d8 = tid & 15;
        float acc[8];
        {
            const __half2* r0 = (const __half2*)&kvh[s * KVSTR + d8 * 8];
            #pragma unroll
            for (int u = 0; u < 4; u++) {
                const float2 v = __half22float2(r0[u]);
                acc[2 * u] = v.x; acc[2 * u + 1] = v.y;
            }
        }
        #pragma unroll
        for (int t = 0; t < 17; t++) {
            const float p = sc[s][t];
            const __half2* rt = (const __half2*)&kvh[t * KVSTR + d8 * 8];
            #pragma unroll
            for (int u = 0; u < 4; u++) {
                const float2 v = __half22float2(rt[u]);
                acc[2 * u]     += p * v.x;
                acc[2 * u + 1] += p * v.y;
            }
        }
        const size_t idx = ((size_t)b * SS + s) * MM + h * HSD + d8 * 8;
        __half2 o[4];
        #pragma unroll
        for (int u = 0; u < 4; u++) o[u] = __floats2half2_rn(acc[2 * u], acc[2 * u + 1]);
        *(uint4*)&g_mph[idx] = *(uint4*)o;
    }
}

// ---------------------------------------------------------------------------
// Kernel C: big fp16 GEMM. z = zbase + blockIdx.z.
// ---------------------------------------------------------------------------
__global__ __launch_bounds__(256, 2) void big_gemm_h(int zbase)
{
    __shared__ __align__(128) char smem[2 * (A_TILE + B_TILE)];
    const int z = zbase + blockIdx.z;
    const int row0 = blockIdx.y * 128, col0 = blockIdx.x * 128;

    const __half* A = (z == 0) ? g_mph : g_hh;
    const __half* W = g_wh + (size_t)z * MM * MM;

    float acc[4][4][4] = {};
    gemm_body_h(A, W, row0, col0, MM / 32, smem, acc);

    const int lane = threadIdx.x & 31, wid = threadIdx.x >> 5;
    const int wr = wid >> 2, wc = wid & 3;
    const int kq = lane & 3, gq = lane >> 2;

    __half* outp = g_acc[z];
    #pragma unroll
    for (int nt = 0; nt < 4; nt++) {
        const int c = col0 + wc * 32 + nt * 8 + 2 * kq;
        #pragma unroll
        for (int mt = 0; mt < 4; mt++) {
            #pragma unroll
            for (int h = 0; h < 2; h++) {
                const int r = row0 + wr * 64 + mt * 16 + gq + h * 8;
                *(__half2*)&outp[(size_t)r * MM + c] =
                    __floats2half2_rn(acc[mt][nt][2 * h + 0], acc[mt][nt][2 * h + 1]);
            }
        }
    }
}

// ---------------------------------------------------------------------------
// Kernel D: streaming gate epilogue (fast-math; fp16 acc/mp/gate-x reads).
// ---------------------------------------------------------------------------
__device__ __forceinline__ void ld4h(float* d, const __half* p) {
    const __half2* h2 = (const __half2*)p;
    const float2 lo = __half22float2(h2[0]), hi = __half22float2(h2[1]);
    d[0] = lo.x; d[1] = lo.y; d[2] = hi.x; d[3] = hi.y;
}

__global__ __launch_bounds__(256) void gate_epilogue(
    const float* __restrict__ mstate,
    const float* __restrict__ bg,  const float* __restrict__ buf_,
    const float* __restrict__ bui, const float* __restrict__ buo,
    float* __restrict__ out)
{
    const size_t e = ((size_t)blockIdx.x * 256 + threadIdx.x) * 4;
    const int r = (int)(e >> 10);
    const int c = (int)(e & 1023);
    const int bidx = r >> 4;

    float vg[4], vf[4], vi[4], vo[4], mp[4], wf[4], wi[4], wo[4];
    ld4h(vg, &g_acc[0][e]);
    ld4h(vf, &g_acc[1][e]);
    ld4h(vi, &g_acc[2][e]);
    ld4h(vo, &g_acc[3][e]);
    ld4h(mp, &g_mph[e]);
    ld4h(wf, &g_xwh[(size_t)0 * BB * MM + (size_t)bidx * MM + c]);
    ld4h(wi, &g_xwh[(size_t)1 * BB * MM + (size_t)bidx * MM + c]);
    ld4h(wo, &g_xwh[(size_t)2 * BB * MM + (size_t)bidx * MM + c]);

    const float4 mv  = *(const float4*)&mstate[e];
    const float4 bgv = *(const float4*)&bg[c];
    const float4 bfv = *(const float4*)&buf_[c];
    const float4 biv = *(const float4*)&bui[c];
    const float4 bov = *(const float4*)&buo[c];

    float nm[4], nh[4];
    const float* mvp = &mv.x;
    const float* bgp = &bgv.x; const float* bfp = &bfv.x;
    const float* bip = &biv.x; const float* bop = &bov.x;
    #pragma unroll
    for (int u = 0; u < 4; u++) {
        const float mpf = vg[u] + bgp[u] + mp[u];
        const float fgt = sigf_fast(vf[u] + bfp[u] + wf[u]);
        const float igt = sigf_fast(vi[u] + bip[u] + wi[u]);
        const float ogt = sigf_fast(vo[u] + bop[u] + wo[u]);
        nm[u] = sigf_fast(mvp[u] * fgt + 1.0f) + mpf * sigf_fast(igt);
        nh[u] = tanh_fast(mvp[u]) * sigf_fast(ogt);
    }
    *(float4*)&out[e]        = *(float4*)nm;
    *(float4*)&out[BSMN + e] = *(float4*)nh;
}

// ---------------------------------------------------------------------------
// Side stream + events (host objects at load time; serial fallback on failure)
// ---------------------------------------------------------------------------
static cudaStream_t g_s2 = 0;
static cudaEvent_t  g_evA = 0, g_evB = 0;
static bool g_use2 = false;
namespace {
struct StreamInit {
    StreamInit() {
        g_use2 =
            cudaStreamCreateWithFlags(&g_s2, cudaStreamNonBlocking) == cudaSuccess &&
            cudaEventCreateWithFlags(&g_evA, cudaEventDisableTiming) == cudaSuccess &&
            cudaEventCreateWithFlags(&g_evB, cudaEventDisableTiming) == cudaSuccess;
    }
};
static StreamInit g_stream_init;
}

// ---------------------------------------------------------------------------
extern "C" void kernel_launch(void* const* d_in, const int* in_sizes, int n_in,
                              void* d_out, int out_size)
{
    const float* inputs  = (const float*)d_in[0];
    const float* h_state = (const float*)d_in[1];
    const float* m_state = (const float*)d_in[2];
    const float* W_emb   = (const float*)d_in[3];
    const float* b_emb   = (const float*)d_in[4];
    const float* W_g     = (const float*)d_in[5];
    const float* b_g     = (const float*)d_in[6];
    const float* W_wf    = (const float*)d_in[7];
    const float* W_wi    = (const float*)d_in[8];
    const float* W_wo    = (const float*)d_in[9];
    const float* W_uf    = (const float*)d_in[10];
    const float* b_uf    = (const float*)d_in[11];
    const float* W_ui    = (const float*)d_in[12];
    const float* b_ui    = (const float*)d_in[13];
    const float* W_uo    = (const float*)d_in[14];
    const float* b_uo    = (const float*)d_in[15];
    float* out = (float*)d_out;

    // fp32 -> fp16 conversions (default stream; R10-proven schedule)
    conv_w<<<dim3(MM * MM / 1024, 1, 8), 256>>>(W_g, W_uf, W_ui, W_uo,
                                                W_emb, W_wf, W_wi, W_wo);
    conv_s<<<(BSR * MM + BB * DD) / 1024, 256>>>(h_state, inputs);

    if (g_use2) {
        cudaEventRecord(g_evA, 0);
        // s1 chain: gemm_x (all 4) -> attn -> big z0
        gemm_x_h<<<dim3(8, 2, 4), 256>>>(b_emb);
        // s2: big GEMMs z1-3 (depend only on conversions)
        cudaStreamWaitEvent(g_s2, g_evA, 0);
        big_gemm_h<<<dim3(8, 32, 3), 256, 0, g_s2>>>(1);
        cudaEventRecord(g_evB, g_s2);
        attn_kernel<<<BB * HH, 256>>>(m_state);
        big_gemm_h<<<dim3(8, 32, 1), 256>>>(0);
        // join before epilogue
        cudaStreamWaitEvent(0, g_evB, 0);
        gate_epilogue<<<(BSR * MM) / (256 * 4), 256>>>(m_state, b_g, b_uf, b_ui, b_uo, out);
    } else {
        gemm_x_h<<<dim3(8, 2, 4), 256>>>(b_emb);
        attn_kernel<<<BB * HH, 256>>>(m_state);
        big_gemm_h<<<dim3(8, 32, 3), 256>>>(1);
        big_gemm_h<<<dim3(8, 32, 1), 256>>>(0);
        gate_epilogue<<<(BSR * MM) / (256 * 4), 256>>>(m_state, b_g, b_uf, b_ui, b_uo, out);
    }
}